// round 1
// baseline (speedup 1.0000x reference)
#include <cuda_runtime.h>

#define BATCH   32
#define SEQ_LEN 4096
#define D_K     128
#define HALF    64            // D_K / 2 rotation frequencies
#define ROW4    (D_K / 4)     // float4 per row = 32
#define THREADS 256

// Correctly-rounded (to fp32) inverse frequencies, recomputed every launch
// (deterministic, no caching) by a tiny fp64 kernel.
__device__ float g_inv_freq[HALF];

__global__ void rope_inv_freq_kernel() {
    int j = threadIdx.x;
    if (j < HALF) {
        // inv_freq[j] = 10000^(-j/64) = 2^(-j * log2(10000)/64), exact in fp64
        double e = -(double)j * (13.287712379549449 / 64.0);
        g_inv_freq[j] = (float)exp2(e);
    }
}

__global__ __launch_bounds__(THREADS) void rope_kernel(
    const float* __restrict__ x,
    const int*   __restrict__ token_positions,
    float*       __restrict__ out)
{
    // cs[j] = {cos(pos*f_j), sin(pos*f_j)}; read back as float4 (pairs 2q,2q+1)
    __shared__ float2 cs[HALF];

    const int p = blockIdx.x;      // one block per sequence position
    const int t = threadIdx.x;

    if (t < HALF) {
        float ang = (float)token_positions[p] * g_inv_freq[t];
        float s, c;
        sincosf(ang, &s, &c);      // precise variant: ~2 ulp incl. arg reduction
        cs[t] = make_float2(c, s);
    }
    __syncthreads();

    const float4* __restrict__ x4 = (const float4*)x;
    float4*       __restrict__ o4 = (float4*)out;
    const float4* __restrict__ csp = (const float4*)cs;   // csp[q] = {c2q,s2q,c2q+1,s2q+1}

    const long rowStride4 = (long)SEQ_LEN * ROW4;         // float4 per batch slab
    const long posBase4   = (long)p * ROW4;

    // 32 batches * 32 float4/row = 1024 float4 per block; 4 iters per thread.
    #pragma unroll
    for (int c = t; c < BATCH * ROW4; c += THREADS) {
        const int  b   = c >> 5;                // batch index
        const int  q   = c & 31;                // float4 index within row
        const long idx = (long)b * rowStride4 + posBase4 + q;

        float4 v  = x4[idx];
        float4 cw = csp[q];                     // {cos0, sin0, cos1, sin1}

        float4 r;
        r.x = v.x * cw.x - v.y * cw.y;          // even0*cos - odd0*sin
        r.y = v.x * cw.y + v.y * cw.x;          // even0*sin + odd0*cos
        r.z = v.z * cw.z - v.w * cw.w;
        r.w = v.z * cw.w + v.w * cw.z;
        o4[idx] = r;
    }
}

extern "C" void kernel_launch(void* const* d_in, const int* in_sizes, int n_in,
                              void* d_out, int out_size) {
    const float* x   = (const float*)d_in[0];
    const int*   pos = (const int*)d_in[1];
    float*       out = (float*)d_out;

    rope_inv_freq_kernel<<<1, HALF>>>();
    rope_kernel<<<SEQ_LEN, THREADS>>>(x, pos, out);
}

// round 2
// speedup vs baseline: 1.0799x; 1.0799x over previous
#include <cuda_runtime.h>

#define BATCH   32
#define SEQ_LEN 4096
#define D_K     128
#define HALF    64            // D_K / 2 rotation frequencies
#define ROW4    (D_K / 4)     // float4 per row = 32
#define THREADS 256
#define ITERS   (BATCH * ROW4 / THREADS)   // 4

__global__ __launch_bounds__(THREADS) void rope_fused_kernel(
    const float* __restrict__ x,
    const int*   __restrict__ token_positions,
    float*       __restrict__ out)
{
    // cs[j] = {cos(pos*f_j), sin(pos*f_j)}; read back as float4 (pairs 2q,2q+1)
    __shared__ float2 cs[HALF];

    const int p = blockIdx.x;      // one block per sequence position
    const int t = threadIdx.x;

    // ---- address math: q = float4-column is invariant across iterations ----
    const int  q          = t & 31;                   // float4 index within row
    const int  b0         = t >> 5;                   // first batch index
    const long rowStride4 = (long)SEQ_LEN * ROW4;     // float4 per batch slab
    const long base       = (long)p * ROW4 + q;

    const float4* __restrict__ x4 = (const float4*)x;
    float4*       __restrict__ o4 = (float4*)out;

    // ---- issue all global loads FIRST (overlap DRAM latency with sincos) ----
    long   idx[ITERS];
    float4 v[ITERS];
    #pragma unroll
    for (int i = 0; i < ITERS; i++) {
        idx[i] = (long)(b0 + 8 * i) * rowStride4 + base;
        v[i]   = x4[idx[i]];
    }

    // ---- threads 0..63: double-float-accurate inv_freq + sincos ----
    if (t < HALF) {
        // L = log2(10000)/64 split into fp32 hi/lo (2 scalar fp64 ops: cast+sub)
        const double Ld   = 0.20762050593046014;      // log2(1e4)/64
        const float  L_hi = (float)Ld;
        const float  L_lo = (float)(Ld - (double)L_hi);

        const float jf    = (float)t;
        const float ehi   = jf * L_hi;
        const float eerr  = fmaf(jf, L_hi, -ehi);     // exact residual of jf*L_hi
        const float elo   = eerr + jf * L_lo;

        // inv_freq = 2^-(ehi+elo) = exp2f(-ehi) * (1 - ln2*elo)  (elo ~ 1e-6)
        float inv = exp2f(-ehi);
        inv = inv - inv * (0.6931471805599453f * elo);

        const float ang = (float)token_positions[p] * inv;
        float s, c;
        sincosf(ang, &s, &c);                         // precise ~2 ulp path
        cs[t] = make_float2(c, s);
    }
    __syncthreads();

    // One smem read per thread: {cos(2q), sin(2q), cos(2q+1), sin(2q+1)}
    const float4 cw = ((const float4*)cs)[q];

    #pragma unroll
    for (int i = 0; i < ITERS; i++) {
        float4 r;
        r.x = v[i].x * cw.x - v[i].y * cw.y;          // even*cos - odd*sin
        r.y = v[i].x * cw.y + v[i].y * cw.x;          // even*sin + odd*cos
        r.z = v[i].z * cw.z - v[i].w * cw.w;
        r.w = v[i].z * cw.w + v[i].w * cw.z;
        o4[idx[i]] = r;
    }
}

extern "C" void kernel_launch(void* const* d_in, const int* in_sizes, int n_in,
                              void* d_out, int out_size) {
    const float* x   = (const float*)d_in[0];
    const int*   pos = (const int*)d_in[1];
    float*       out = (float*)d_out;

    rope_fused_kernel<<<SEQ_LEN, THREADS>>>(x, pos, out);
}